// round 1
// baseline (speedup 1.0000x reference)
#include <cuda_runtime.h>
#include <math.h>

#define Bn 1024
#define Pn 8
#define Dn 2048
#define PDn (Pn * Dn)      // 16384
#define NUM_IDS 64
#define MARGIN 0.3f
#define EPSV 1e-12f

// ---------------- device scratch (static; no allocations) ----------------
__device__ int   g_lab[Bn];                   // normalized int labels
__device__ int   g_idx[NUM_IDS * Bn];         // per-id sample index lists
__device__ int   g_cnt[NUM_IDS];
__device__ float g_centers[NUM_IDS * PDn];    // 4 MB
__device__ float g_sq[Bn * Pn];               // ||f[i,p]||^2
__device__ float g_dpp[Bn * Pn];              // sqrt dist to center per (i,p)
__device__ float g_dap[Bn];                   // sum over p
__device__ float g_dpair[(size_t)Pn * Bn * Bn]; // 32 MB: sqrt pair dist per p
__device__ float g_part[256 * 2];             // per-block (sum_val, sum_mask)

// ---------------- K0: normalize labels (int32/int64 autodetect) + lists ----
__global__ void build_kernel(const int* __restrict__ raw) {
    __shared__ int is64;
    int t = threadIdx.x; // 256 threads
    if (t == 0) is64 = 1;
    __syncthreads();
    // If labels are int64 (LE), odd 32-bit words of the first 1024 ints are 0.
    for (int k = t; k < 512; k += 256) {
        if (raw[2 * k + 1] != 0) is64 = 0;  // benign race: only writes 0
    }
    __syncthreads();
    int w64 = is64;
    for (int b = t; b < Bn; b += 256) {
        g_lab[b] = w64 ? raw[2 * b] : raw[b];
    }
    __syncthreads();
    if (t < NUM_IDS) {
        int c = 0;
        for (int b = 0; b < Bn; b++) {
            if (g_lab[b] == t) g_idx[t * Bn + (c++)] = b;
        }
        g_cnt[t] = c;
    }
}

// ---------------- K1: class centers (segment mean, gather form) ----------
__global__ void centers_kernel(const float* __restrict__ f) {
    int id  = blockIdx.y;
    int dim = blockIdx.x * 256 + threadIdx.x;   // 0..16383
    int cnt = g_cnt[id];
    float acc = 0.f;
    const int* lst = g_idx + id * Bn;
    for (int s = 0; s < cnt; s++) {
        acc += f[(size_t)lst[s] * PDn + dim];
    }
    g_centers[(size_t)id * PDn + dim] = acc / fmaxf((float)cnt, 1.0f);
}

// ---------------- K2: per-(i,p) dist-to-center and squared norm ----------
__global__ void dap_kernel(const float* __restrict__ f) {
    int i = blockIdx.x;
    int p = blockIdx.y;
    int tid = threadIdx.x;
    const float* fr = f + (size_t)i * PDn + (size_t)p * Dn;
    const float* cr = g_centers + (size_t)g_lab[i] * PDn + (size_t)p * Dn;
    float d = 0.f, s = 0.f;
    for (int k = tid; k < Dn; k += 256) {
        float v = fr[k];
        float e = v - cr[k];
        d += e * e;
        s += v * v;
    }
    __shared__ float sd[256], ss[256];
    sd[tid] = d; ss[tid] = s;
    __syncthreads();
    for (int o = 128; o > 0; o >>= 1) {
        if (tid < o) { sd[tid] += sd[tid + o]; ss[tid] += ss[tid + o]; }
        __syncthreads();
    }
    if (tid == 0) {
        g_dpp[i * Pn + p] = sqrtf(fmaxf(sd[0], EPSV));
        g_sq[i * Pn + p]  = ss[0];
    }
}

// ---------------- K2b: d_ap[i] = sum_p ---------------------------------
__global__ void dapsum_kernel() {
    int i = blockIdx.x * 256 + threadIdx.x;
    if (i < Bn) {
        float s = 0.f;
        #pragma unroll
        for (int p = 0; p < Pn; p++) s += g_dpp[i * Pn + p];
        g_dap[i] = s;
    }
}

// ---------------- K3: 128x128 fp32 GEMM per (tile_i, tile_j, p) ----------
// acc = f[i,p,:] . f[j,p,:], then g_dpair[p][i][j] = sqrt(max(sqi+sqj-2acc,eps))
__global__ void __launch_bounds__(256) gemm_kernel(const float* __restrict__ f) {
    int p  = blockIdx.z;
    int ti = blockIdx.y * 128;
    int tj = blockIdx.x * 128;

    __shared__ float As[16][132];
    __shared__ float Bs[16][132];

    int tid = threadIdx.x;
    int tm = (tid >> 4) << 3;   // 0..120, step 8
    int tn = (tid & 15) << 3;

    const float* Ab = f + (size_t)ti * PDn + (size_t)p * Dn;
    const float* Bb = f + (size_t)tj * PDn + (size_t)p * Dn;

    float acc[8][8];
    #pragma unroll
    for (int a = 0; a < 8; a++)
        #pragma unroll
        for (int b = 0; b < 8; b++) acc[a][b] = 0.f;

    for (int kt = 0; kt < Dn; kt += 16) {
        #pragma unroll
        for (int l = 0; l < 2; l++) {
            int idx = tid + (l << 8);      // 0..511
            int row = idx >> 2;            // 0..127
            int c4  = idx & 3;             // float4 within 16-wide k-slab
            float4 av = *(const float4*)(Ab + (size_t)row * PDn + kt + (c4 << 2));
            float4 bv = *(const float4*)(Bb + (size_t)row * PDn + kt + (c4 << 2));
            int kk = c4 << 2;
            As[kk + 0][row] = av.x; As[kk + 1][row] = av.y;
            As[kk + 2][row] = av.z; As[kk + 3][row] = av.w;
            Bs[kk + 0][row] = bv.x; Bs[kk + 1][row] = bv.y;
            Bs[kk + 2][row] = bv.z; Bs[kk + 3][row] = bv.w;
        }
        __syncthreads();
        #pragma unroll
        for (int k = 0; k < 16; k++) {
            float4 a0 = *(const float4*)&As[k][tm];
            float4 a1 = *(const float4*)&As[k][tm + 4];
            float4 b0 = *(const float4*)&Bs[k][tn];
            float4 b1 = *(const float4*)&Bs[k][tn + 4];
            float ar[8] = {a0.x, a0.y, a0.z, a0.w, a1.x, a1.y, a1.z, a1.w};
            float br[8] = {b0.x, b0.y, b0.z, b0.w, b1.x, b1.y, b1.z, b1.w};
            #pragma unroll
            for (int ii = 0; ii < 8; ii++)
                #pragma unroll
                for (int jj = 0; jj < 8; jj++)
                    acc[ii][jj] += ar[ii] * br[jj];
        }
        __syncthreads();
    }

    float sqa[8], sqb[8];
    #pragma unroll
    for (int ii = 0; ii < 8; ii++) sqa[ii] = g_sq[(ti + tm + ii) * Pn + p];
    #pragma unroll
    for (int jj = 0; jj < 8; jj++) sqb[jj] = g_sq[(tj + tn + jj) * Pn + p];

    size_t pbase = (size_t)p << 20;
    #pragma unroll
    for (int ii = 0; ii < 8; ii++) {
        size_t rbase = pbase + ((size_t)(ti + tm + ii) << 10) + (tj + tn);
        #pragma unroll
        for (int jj = 0; jj < 8; jj++) {
            float d2 = sqa[ii] + sqb[jj] - 2.0f * acc[ii][jj];
            g_dpair[rbase + jj] = sqrtf(fmaxf(d2, EPSV));
        }
    }
}

// ---------------- K4: masked margin reduction (per-block partials) -------
__global__ void epilogue_kernel() {
    int tid = threadIdx.x;
    float accv = 0.f, accm = 0.f;
    int base = blockIdx.x * 4096;
    for (int t = 0; t < 16; t++) {
        int idx = base + t * 256 + tid;     // 0 .. 1M-1
        int i = idx >> 10, j = idx & 1023;
        if (g_lab[i] != g_lab[j]) {
            float daa = 0.f;
            #pragma unroll
            for (int p = 0; p < Pn; p++)
                daa += g_dpair[((size_t)p << 20) + idx];
            float v = g_dap[i] + g_dap[j] - daa + MARGIN;
            accv += fmaxf(v, 0.f);
            accm += 1.f;
        }
    }
    __shared__ float sv[256], sm[256];
    sv[tid] = accv; sm[tid] = accm;
    __syncthreads();
    for (int o = 128; o > 0; o >>= 1) {
        if (tid < o) { sv[tid] += sv[tid + o]; sm[tid] += sm[tid + o]; }
        __syncthreads();
    }
    if (tid == 0) {
        g_part[blockIdx.x * 2 + 0] = sv[0];
        g_part[blockIdx.x * 2 + 1] = sm[0];
    }
}

// ---------------- K5: finalize -------------------------------------------
__global__ void finalize_kernel(float* __restrict__ out) {
    int tid = threadIdx.x; // 256
    __shared__ float sv[256], sm[256];
    sv[tid] = g_part[tid * 2 + 0];
    sm[tid] = g_part[tid * 2 + 1];
    __syncthreads();
    for (int o = 128; o > 0; o >>= 1) {
        if (tid < o) { sv[tid] += sv[tid + o]; sm[tid] += sm[tid + o]; }
        __syncthreads();
    }
    if (tid == 0) out[0] = sv[0] / sm[0];
}

// ---------------- launch --------------------------------------------------
extern "C" void kernel_launch(void* const* d_in, const int* in_sizes, int n_in,
                              void* d_out, int out_size) {
    const float* f     = (const float*)d_in[0];
    const int*   labr  = (const int*)d_in[1];   // int32 or int64 storage; autodetected
    float*       out   = (float*)d_out;

    build_kernel<<<1, 256>>>(labr);
    centers_kernel<<<dim3(PDn / 256, NUM_IDS), 256>>>(f);
    dap_kernel<<<dim3(Bn, Pn), 256>>>(f);
    dapsum_kernel<<<4, 256>>>();
    gemm_kernel<<<dim3(8, 8, 8), 256>>>(f);
    epilogue_kernel<<<256, 256>>>();
    finalize_kernel<<<1, 256>>>(out);
}